// round 4
// baseline (speedup 1.0000x reference)
#include <cuda_runtime.h>
#include <cstdint>

// SpatialTransformer bilinear flow warp.
// src:  [B,H,W,1] f32,  flow: [B,H,W,2] f32,  out: [B,H,W,1] f32
// B=32, H=768, W=768.
//
// Layout: 32x32 pixel tile per block (256 threads).
//   lane -> x within tile (warp = 32 consecutive x -> coalesced gathers)
//   warp -> 4-row vertical strip (L1 reuse of bilinear row halo)
//
// __launch_bounds__(256, 4): grants a 64-register budget so ptxas can keep
// all 16 gathers + 4 flow loads in flight (R3 showed that at 32 regs it
// re-serializes the batch and MLP collapses to ~4).

#define BB 32
#define HH 768
#define WW 768
#define HW (HH * WW)

__global__ __launch_bounds__(256, 4) void warp_kernel(
    const float* __restrict__ src,
    const float* __restrict__ flow,
    float* __restrict__ out)
{
    const int tx = threadIdx.x;
    const int xg = blockIdx.x * 32 + (tx & 31);
    const int yb = blockIdx.y * 32 + (tx >> 5) * 4;
    const int b  = blockIdx.z;

    const float* img  = src + b * HW;
    const int    pix0 = (b * HH + yb) * WW + xg;
    const float  xgf  = (float)xg;

    // ---- phase 1: all flow loads up front (4 independent LDG.64) ----
    float2 f[4];
    #pragma unroll
    for (int r = 0; r < 4; r++)
        f[r] = *reinterpret_cast<const float2*>(flow + (size_t)(pix0 + r * WW) * 2);

    // ---- phase 2: all weights + addresses ----
    float wa[4], wb[4], wc[4], wd[4];
    int   a00[4], a01[4], a10[4], a11[4];

    #pragma unroll
    for (int r = 0; r < 4; r++) {
        const float gx = xgf + f[r].x;
        const float gy = (float)(yb + r) + f[r].y;

        const float x0f = floorf(gx);
        const float y0f = floorf(gy);
        const float x1f = x0f + 1.0f;
        const float y1f = y0f + 1.0f;

        const float dx1 = x1f - gx;
        const float dx0 = gx - x0f;
        const float dy1 = y1f - gy;
        const float dy0 = gy - y0f;

        wa[r] = dx1 * dy1;
        wb[r] = dx0 * dy1;
        wc[r] = dx1 * dy0;
        wd[r] = dx0 * dy0;

        const int xi0 = (int)fminf(fmaxf(x0f, 0.0f), (float)(WW - 1));
        const int xi1 = (int)fminf(fmaxf(x1f, 0.0f), (float)(WW - 1));
        const int yi0 = (int)fminf(fmaxf(y0f, 0.0f), (float)(HH - 1));
        const int yi1 = (int)fminf(fmaxf(y1f, 0.0f), (float)(HH - 1));

        const int r0 = yi0 * WW;
        const int r1 = yi1 * WW;
        a00[r] = r0 + xi0;
        a01[r] = r0 + xi1;
        a10[r] = r1 + xi0;
        a11[r] = r1 + xi1;
    }

    // ---- phase 3: all 16 gathers back-to-back (MLP = 16) ----
    float va[4], vb[4], vc[4], vd[4];
    #pragma unroll
    for (int r = 0; r < 4; r++) va[r] = __ldg(img + a00[r]);
    #pragma unroll
    for (int r = 0; r < 4; r++) vb[r] = __ldg(img + a01[r]);
    #pragma unroll
    for (int r = 0; r < 4; r++) vc[r] = __ldg(img + a10[r]);
    #pragma unroll
    for (int r = 0; r < 4; r++) vd[r] = __ldg(img + a11[r]);

    // ---- phase 4: combine + store ----
    #pragma unroll
    for (int r = 0; r < 4; r++) {
        out[pix0 + r * WW] =
            wa[r] * va[r] + wb[r] * vb[r] + wc[r] * vc[r] + wd[r] * vd[r];
    }
}

extern "C" void kernel_launch(void* const* d_in, const int* in_sizes, int n_in,
                              void* d_out, int out_size)
{
    const float* src  = (const float*)d_in[0];
    const float* flow = (const float*)d_in[1];
    float* out = (float*)d_out;

    dim3 grid(WW / 32, HH / 32, BB);   // (24, 24, 32)
    warp_kernel<<<grid, 256>>>(src, flow, out);
}

// round 5
// speedup vs baseline: 1.3255x; 1.3255x over previous
#include <cuda_runtime.h>
#include <cstdint>

// SpatialTransformer bilinear flow warp.
// src:  [B,H,W,1] f32,  flow: [B,H,W,2] f32,  out: [B,H,W,1] f32
// B=32, H=768, W=768.
//
// Layout: 32x16 pixel tile per block (128 threads = 4 warps).
//   lane -> x within tile (warp = 32 consecutive x -> coalesced gathers)
//   warp -> 4-row vertical strip (L1 reuse of bilinear row halo)
// 128-thread blocks let the SM pack 16 blocks = 64 warps = ~100% occupancy
// (R2's 256-thread blocks quantized to 56 warps = 87%). R4 proved occupancy,
// not per-thread MLP, is what hides the gather latency on sm_103a.

#define BB 32
#define HH 768
#define WW 768
#define HW (HH * WW)

__global__ __launch_bounds__(128) void warp_kernel(
    const float* __restrict__ src,
    const float* __restrict__ flow,
    float* __restrict__ out)
{
    const int tx = threadIdx.x;
    const int xg = blockIdx.x * 32 + (tx & 31);       // global x
    const int yb = blockIdx.y * 16 + (tx >> 5) * 4;   // first of 4 rows
    const int b  = blockIdx.z;

    const float* img = src + b * HW;
    const float  xgf = (float)xg;

    #pragma unroll
    for (int r = 0; r < 4; r++) {
        const int y   = yb + r;
        const int pix = (b * HH + y) * WW + xg;

        const float2 f = *reinterpret_cast<const float2*>(flow + (size_t)pix * 2);

        const float gx = xgf + f.x;
        const float gy = (float)y + f.y;

        const float x0f = floorf(gx);
        const float y0f = floorf(gy);
        const float x1f = x0f + 1.0f;
        const float y1f = y0f + 1.0f;

        // bilinear weights from UNCLIPPED corners (matches reference)
        const float dx1 = x1f - gx;
        const float dx0 = gx - x0f;
        const float dy1 = y1f - gy;
        const float dy0 = gy - y0f;

        const float wa = dx1 * dy1;
        const float wb = dx0 * dy1;
        const float wc = dx1 * dy0;
        const float wd = dx0 * dy0;

        // clipped integer indices
        const int xi0 = (int)fminf(fmaxf(x0f, 0.0f), (float)(WW - 1));
        const int xi1 = (int)fminf(fmaxf(x1f, 0.0f), (float)(WW - 1));
        const int yi0 = (int)fminf(fmaxf(y0f, 0.0f), (float)(HH - 1));
        const int yi1 = (int)fminf(fmaxf(y1f, 0.0f), (float)(HH - 1));

        const int r0 = yi0 * WW;
        const int r1 = yi1 * WW;

        const float va = __ldg(img + r0 + xi0);
        const float vb = __ldg(img + r0 + xi1);
        const float vc = __ldg(img + r1 + xi0);
        const float vd = __ldg(img + r1 + xi1);

        out[pix] = wa * va + wb * vb + wc * vc + wd * vd;
    }
}

extern "C" void kernel_launch(void* const* d_in, const int* in_sizes, int n_in,
                              void* d_out, int out_size)
{
    const float* src  = (const float*)d_in[0];
    const float* flow = (const float*)d_in[1];
    float* out = (float*)d_out;

    dim3 grid(WW / 32, HH / 16, BB);   // (24, 48, 32)
    warp_kernel<<<grid, 128>>>(src, flow, out);
}